// round 1
// baseline (speedup 1.0000x reference)
#include <cuda_runtime.h>
#include <math.h>

#define NDIM 256
#define N3   16777216u           // 256^3
#define NBP  132                 // padded bin count (need 129: labels 0..128)

// Scratch: 2 complex volumes (ref+i*pred packed), 268MB. Device globals are the
// sanctioned scratch mechanism (no cudaMalloc allowed).
__device__ float2 g_work[2u * N3];
// Accumulators: [vol][label*3 + comp], comp = {S0, S1, S2}. 2*400 doubles.
__device__ double g_bins[800];

// ---------------------------------------------------------------------------
// In-register 16-point radix-2 DIT FFT (forward, e^{-2*pi*i*nk/N}).
// ---------------------------------------------------------------------------
__constant__ float TW16C[8] = { 1.0f,  0.9238795325112867f,  0.7071067811865476f,
                                0.3826834323650898f, 0.0f, -0.3826834323650898f,
                               -0.7071067811865476f, -0.9238795325112867f };
__constant__ float TW16S[8] = { 0.0f, -0.3826834323650898f, -0.7071067811865476f,
                               -0.9238795325112867f, -1.0f, -0.9238795325112867f,
                               -0.7071067811865476f, -0.3826834323650898f };

__device__ __forceinline__ void cswap(float2& a, float2& b) { float2 t = a; a = b; b = t; }

__device__ __forceinline__ void fft16(float2 v[16]) {
    // bit-reversal permutation (4-bit)
    cswap(v[1], v[8]);  cswap(v[2], v[4]);  cswap(v[3], v[12]);
    cswap(v[5], v[10]); cswap(v[7], v[14]); cswap(v[11], v[13]);
#pragma unroll
    for (int s = 1; s <= 4; s++) {
        const int m = 1 << s, hm = m >> 1;
#pragma unroll
        for (int k = 0; k < 16; k += m) {
#pragma unroll
            for (int j = 0; j < hm; j++) {
                const float wr = TW16C[j << (4 - s)];
                const float wi = TW16S[j << (4 - s)];
                float2 a = v[k + j], b = v[k + j + hm];
                float tr = b.x * wr - b.y * wi;
                float ti = b.x * wi + b.y * wr;
                v[k + j]      = make_float2(a.x + tr, a.y + ti);
                v[k + j + hm] = make_float2(a.x - tr, a.y - ti);
            }
        }
    }
}

// ---------------------------------------------------------------------------
// Pass 0: pack (ref + i*pred) and FFT along W (contiguous dim).
// Block = 256 threads = 16 lines x 16 threads. Each thread: 16 elements.
// grid = 2 vols * 4096 tiles.
// ---------------------------------------------------------------------------
__global__ void k_pass0(const float* __restrict__ ref, const float* __restrict__ pred) {
    __shared__ float2 sh[16 * 273];   // per-line 272 (stride 17), padded stride 273
    __shared__ float2 tw[256];        // W_256^m table

    const int tid = threadIdx.x;
    {
        float s, c;
        sincospif(-(float)tid / 128.0f, &s, &c);
        tw[tid] = make_float2(c, s);
    }
    const int bid  = blockIdx.x;
    const unsigned vol  = (unsigned)bid >> 12;
    const unsigned tile = (unsigned)bid & 4095u;
    const int l = tid >> 4;    // line in tile
    const int t = tid & 15;    // FFT thread index (n2 digit)
    const unsigned base = vol * N3 + (tile * 16u + (unsigned)l) * 256u;

    float2 v[16];
#pragma unroll
    for (int n1 = 0; n1 < 16; n1++) {
        unsigned e = base + (unsigned)(n1 * 16 + t);
        v[n1] = make_float2(ref[e], pred[e]);
    }
    __syncthreads();   // tw ready

    fft16(v);          // over n1 -> k1
#pragma unroll
    for (int k1 = 0; k1 < 16; k1++) {          // twiddle W_256^{t*k1}
        float2 w = tw[t * k1];
        float xr = v[k1].x * w.x - v[k1].y * w.y;
        float xi = v[k1].x * w.y + v[k1].y * w.x;
        v[k1] = make_float2(xr, xi);
    }
    float2* lb = &sh[l * 273];
#pragma unroll
    for (int k1 = 0; k1 < 16; k1++) lb[t * 17 + k1] = v[k1];
    __syncthreads();
#pragma unroll
    for (int n2 = 0; n2 < 16; n2++) v[n2] = lb[n2 * 17 + t];
    fft16(v);          // over n2 -> k2; thread holds X[t + 16*k2]
#pragma unroll
    for (int k2 = 0; k2 < 16; k2++)
        g_work[base + (unsigned)(k2 * 16 + t)] = v[k2];
}

// ---------------------------------------------------------------------------
// Strided FFT pass (H: es=256, outerStride=65536; D: es=65536, outerStride=256).
// Tile = 16 lines at consecutive w (unit stride) for coalescing.
// Threads: wl = tid&15 (line), t = tid>>4 (FFT thread index).
// ---------------------------------------------------------------------------
__global__ void k_passS(unsigned es, unsigned outerStride) {
    __shared__ float2 sh[16 * 273];
    __shared__ float2 tw[256];

    const int tid = threadIdx.x;
    {
        float s, c;
        sincospif(-(float)tid / 128.0f, &s, &c);
        tw[tid] = make_float2(c, s);
    }
    const int bid = blockIdx.x;
    const unsigned vol   = (unsigned)bid >> 12;
    const unsigned r     = (unsigned)bid & 4095u;
    const unsigned outer = r >> 4;
    const unsigned w0    = (r & 15u) * 16u;
    const int wl = tid & 15;
    const int t  = tid >> 4;
    const unsigned base = vol * N3 + outer * outerStride + w0 + (unsigned)wl;

    float2 v[16];
#pragma unroll
    for (int n1 = 0; n1 < 16; n1++)
        v[n1] = g_work[base + (unsigned)(n1 * 16 + t) * es];
    __syncthreads();

    fft16(v);
#pragma unroll
    for (int k1 = 0; k1 < 16; k1++) {
        float2 w = tw[t * k1];
        float xr = v[k1].x * w.x - v[k1].y * w.y;
        float xi = v[k1].x * w.y + v[k1].y * w.x;
        v[k1] = make_float2(xr, xi);
    }
    float2* lb = &sh[wl * 273];
#pragma unroll
    for (int k1 = 0; k1 < 16; k1++) lb[t * 17 + k1] = v[k1];
    __syncthreads();
#pragma unroll
    for (int n2 = 0; n2 < 16; n2++) v[n2] = lb[n2 * 17 + t];
    fft16(v);
#pragma unroll
    for (int k2 = 0; k2 < 16; k2++)
        g_work[base + (unsigned)(k2 * 16 + t) * es] = v[k2];
}

// ---------------------------------------------------------------------------
// Reduction: per k accumulate S0 = |Z(k)|^2, S1 = Re(Z(k)Z(-k)), S2 = Im(Z(k)Z(-k))
// into shell bins. 16 privatized shared fp32 bin copies (warp x lane parity),
// block-flush via double global atomics. Blocks [0,G/2) -> vol 0, rest vol 1.
// ---------------------------------------------------------------------------
__global__ void k_reduce() {
    __shared__ float sb[16][3 * NBP];   // 16 copies * 396 floats = 25344 B
    const int tid = threadIdx.x;
    for (int i = tid; i < 16 * 3 * NBP; i += 256) ((float*)sb)[i] = 0.0f;
    __syncthreads();

    float* bins = sb[((tid >> 5) << 1) | (tid & 1)];

    const unsigned halfGrid = gridDim.x >> 1;
    const unsigned vol = (blockIdx.x >= halfGrid) ? 1u : 0u;
    const unsigned blk = blockIdx.x - vol * halfGrid;
    const unsigned volBase = vol * N3;
    const unsigned nquad = N3 / 2u;             // pairs of complex (w even, w+1)
    const unsigned stride = halfGrid * 256u;

    for (unsigned q = blk * 256u + (unsigned)tid; q < nquad; q += stride) {
        const unsigned f = q * 2u;
        const float4 zz = *reinterpret_cast<const float4*>(&g_work[volBase + f]);
        const unsigned d = f >> 16, h = (f >> 8) & 255u, w = f & 255u;
        const unsigned pd = (256u - d) & 255u, ph = (256u - h) & 255u;
        const unsigned pbase = volBase + (pd << 16) + (ph << 8);
        const float2 m0 = g_work[pbase + ((256u - w) & 255u)];
        const float2 m1 = g_work[pbase + (255u - w)];

        const int sd = (d < 128u) ? (int)d : (int)d - 256;
        const int sh2 = (h < 128u) ? (int)h : (int)h - 256;
        const int sw = (w < 128u) ? (int)w : (int)w - 256;
        const int sw1 = (w + 1u < 128u) ? (int)w + 1 : (int)w - 255;
        const int c2 = sd * sd + sh2 * sh2;
        int l0 = (int)__fsqrt_rn((float)(c2 + sw * sw));
        int l1 = (int)__fsqrt_rn((float)(c2 + sw1 * sw1));
        l0 = min(l0, 128); l1 = min(l1, 128);

        const float a0 = zz.x, b0 = zz.y, a1 = zz.z, b1 = zz.w;
        const float s0a = a0 * a0 + b0 * b0;
        const float s1a = a0 * m0.x - b0 * m0.y;
        const float s2a = a0 * m0.y + b0 * m0.x;
        const float s0b = a1 * a1 + b1 * b1;
        const float s1b = a1 * m1.x - b1 * m1.y;
        const float s2b = a1 * m1.y + b1 * m1.x;

        if (l0 == l1) {
            atomicAdd(&bins[l0 * 3 + 0], s0a + s0b);
            atomicAdd(&bins[l0 * 3 + 1], s1a + s1b);
            atomicAdd(&bins[l0 * 3 + 2], s2a + s2b);
        } else {
            atomicAdd(&bins[l0 * 3 + 0], s0a);
            atomicAdd(&bins[l0 * 3 + 1], s1a);
            atomicAdd(&bins[l0 * 3 + 2], s2a);
            atomicAdd(&bins[l1 * 3 + 0], s0b);
            atomicAdd(&bins[l1 * 3 + 1], s1b);
            atomicAdd(&bins[l1 * 3 + 2], s2b);
        }
    }
    __syncthreads();

    for (int i = tid; i < 3 * 129; i += 256) {
        float s = 0.0f;
#pragma unroll
        for (int cpy = 0; cpy < 16; cpy++) s += sb[cpy][i];
        atomicAdd(&g_bins[vol * 400u + (unsigned)i], (double)s);
    }
}

// ---------------------------------------------------------------------------
// Finalize: fsc^2 = (S2/2)^2 / ((S0+S1)/2 * (S0-S1)/2 + 1e-8); loss = 1 - mean.
// ---------------------------------------------------------------------------
__global__ void k_final(float* out) {
    __shared__ double red[256];
    const int tid = threadIdx.x;
    const unsigned vol = (unsigned)tid >> 7;
    const unsigned bin = (unsigned)tid & 127u;
    const double S0 = g_bins[vol * 400u + bin * 3u + 0u];
    const double S1 = g_bins[vol * 400u + bin * 3u + 1u];
    const double S2 = g_bins[vol * 400u + bin * 3u + 2u];
    const double num = 0.5 * S2;
    const double d1 = 0.5 * (S0 + S1);
    const double d2 = 0.5 * (S0 - S1);
    const double f2 = (num * num) / (d1 * d2 + 1e-8);
    red[tid] = f2;
    __syncthreads();
    for (int s = 128; s > 0; s >>= 1) {
        if (tid < s) red[tid] += red[tid + s];
        __syncthreads();
    }
    if (tid == 0) out[0] = (float)(1.0 - red[0] / 256.0);
}

__global__ void k_zero() {
    int i = blockIdx.x * blockDim.x + threadIdx.x;
    if (i < 800) g_bins[i] = 0.0;
}

// ---------------------------------------------------------------------------
extern "C" void kernel_launch(void* const* d_in, const int* in_sizes, int n_in,
                              void* d_out, int out_size) {
    const float* ref  = (const float*)d_in[0];
    const float* pred = (const float*)d_in[1];
    float* out = (float*)d_out;

    k_zero<<<4, 256>>>();
    k_pass0<<<8192, 256>>>(ref, pred);            // FFT along W (+pack)
    k_passS<<<8192, 256>>>(256u, 65536u);         // FFT along H
    k_passS<<<8192, 256>>>(65536u, 256u);         // FFT along D
    k_reduce<<<2048, 256>>>();                    // shell binning
    k_final<<<1, 256>>>(out);                     // scalar loss
}